// round 6
// baseline (speedup 1.0000x reference)
#include <cuda_runtime.h>
#include <math.h>

#define C_B  8
#define C_J  22
#define C_F  14
#define A_MAX 7.25f
#define S_MAX 9.25f
#define SIG_K (3.14f / (1.732f * 0.5f))

// Single CTA, 128 threads = 4 warps; each warp owns TWO batches via 16-lane
// groups. Lane k (k<11) of a group computes BOTH the attacker-k term and the
// defender-(k+11) term (independent FP chains -> pure ILP), so the reduction
// is a 4-level (8,4,2,1) butterfly confined to the 16-lane group.
// team[j] = (j<11) by construction; out[b] = (sum rec_k p_att_k) *
// prod(1 - p_def_k) + 1e-3. Approx intrinsics keep error ~1e-6 << 1e-3.
__device__ __forceinline__ float p_int_term(const float* __restrict__ row,
                                            float fx, float fy, float Tt) {
    const float px = __ldg(row + 1), py = __ldg(row + 2);
    const float vx = __ldg(row + 3), vy = __ldg(row + 4);

    const float dx = fx - px;
    const float dy = fy - py;
    const float d2 = fmaf(dx, dx, dy * dy);
    const float invd = rsqrtf(d2);
    const float d = d2 * invd;

    float s0 = fmaf(dx, vx, dy * vy) * invd;
    s0 = fminf(fmaxf(s0, -S_MAX), S_MAX);

    const float t_lt1 = (S_MAX - s0) * (1.0f / A_MAX);
    const float d_lt1 = t_lt1 * (s0 + S_MAX) * 0.5f;
    const float sa = s0 * (1.0f / A_MAX);
    const float t_lt2 = sqrtf(fmaf(sa, sa, 2.0f * d * (1.0f / A_MAX))) - sa;

    const float t_lt = (d_lt1 > d) ? t_lt2 : t_lt1;
    const float d_lt = fminf(fmaxf(d_lt1, 0.0f), d);
    const float t_tot = fmaf(d - d_lt, 1.0f / S_MAX, t_lt);

    return 1.0f / (1.0f + __expf(SIG_K * (t_tot - Tt)));
}

__global__ void __launch_bounds__(128, 1)
comp_prob_kernel(const float* __restrict__ frame, float* __restrict__ out) {
    const int lane = threadIdx.x & 31;
    const int g    = lane >> 4;                  // group within warp (0/1)
    const int k    = lane & 15;                  // lane within group
    const int b    = (threadIdx.x >> 5) * 2 + g; // batch

    const float* row0 = frame + b * C_J * C_F;

    // Per-batch scalars: issue these loads unconditionally/first so they
    // overlap with the per-player loads in the L1tex queue.
    const float bxf = __ldg(row0 + 11);
    const float byf = __ldg(row0 + 12);
    const float tof = __ldg(row0 + 13);

    float q = 1.0f;   // defender product term
    float s = 0.0f;   // attacker gather term

    if (k < 11) {
        // Selected field cell: x = int(bx)+0.5, y = (int(by)+1)-0.5
        const float fx = (float)((int)bxf) + 0.5f;
        const float fy = (float)((int)byf) + 0.5f;
        // T[round(tof)-1] = 0.1 * round(tof)
        const float Tt = 0.1f * rintf(tof);

        // attacker k  (team=1): contributes rec_k * p
        const float rec = __ldg(row0 + k * C_F + 10);
        const float p_att = p_int_term(row0 + k * C_F, fx, fy, Tt);
        s = rec * p_att;

        // defender k+11 (team=0): contributes (1 - p)
        const float p_def = p_int_term(row0 + (k + 11) * C_F, fx, fy, Tt);
        q = 1.0f - p_def;
    }

    // 4-level butterfly confined to the 16-lane group.
    #pragma unroll
    for (int o = 8; o > 0; o >>= 1) {
        q *= __shfl_xor_sync(0xFFFFFFFFu, q, o);
        s += __shfl_xor_sync(0xFFFFFFFFu, s, o);
    }

    if (k == 0) out[b] = fmaf(s, q, 0.001f);
}

extern "C" void kernel_launch(void* const* d_in, const int* in_sizes, int n_in,
                              void* d_out, int out_size) {
    comp_prob_kernel<<<1, 128>>>((const float*)d_in[0], (float*)d_out);
}

// round 7
// speedup vs baseline: 1.1840x; 1.1840x over previous
#include <cuda_runtime.h>
#include <math.h>

#define C_B  8
#define C_J  22
#define C_F  14
#define A_MAX 7.25f
#define S_MAX 9.25f
#define SIG_K (3.14f / (1.732f * 0.5f))

// R4 structure (best measured: 4.32us): single CTA, 256 threads, warp b owns
// batch b, lane j owns player j -- 8 light warps hide the load round-trip
// better than 4 heavy ones (R5 regression). team[j] = (j<11) by construction:
//   lanes 0..10  (attackers): s = rec_j * p_j, q = 1
//   lanes 11..21 (defenders): q = 1 - p_j,     s = 0
// out[b] = (sum rec p) * prod(1-p) + 1e-3 via one (product,sum) butterfly.
// New this round: sigmoid via HW tanh.approx.f32 (one MUFU trip instead of
// EX2+RCP two-trip): sigmoid(x) = 0.5*tanh(x/2) + 0.5. |err| ~ 2^-11 << 1e-3.
__device__ __forceinline__ float fast_sigmoid(float x) {
    float t;
    asm("tanh.approx.f32 %0, %1;" : "=f"(t) : "f"(0.5f * x));
    return fmaf(0.5f, t, 0.5f);
}

__global__ void __launch_bounds__(256, 1)
comp_prob_kernel(const float* __restrict__ frame, float* __restrict__ out) {
    const int b = threadIdx.x >> 5;   // warp = batch
    const int j = threadIdx.x & 31;   // lane = player

    const float* row0 = frame + b * C_J * C_F;

    float q = 1.0f;
    float s = 0.0f;

    if (j < C_J) {
        const float* row = row0 + j * C_F;

        const float px = __ldg(row + 1), py = __ldg(row + 2);
        const float vx = __ldg(row + 3), vy = __ldg(row + 4);
        const float rec = (j < 11) ? __ldg(row + 10) : 0.0f;
        const float bxf = __ldg(row0 + 11);
        const float byf = __ldg(row0 + 12);
        const float tof = __ldg(row0 + 13);

        // Selected field cell: x = int(bx)+0.5, y = (int(by)+1)-0.5
        const float fx = (float)((int)bxf) + 0.5f;
        const float fy = (float)((int)byf) + 0.5f;

        const float dx = fx - px;
        const float dy = fy - py;
        const float d2 = fmaf(dx, dx, dy * dy);
        const float invd = rsqrtf(d2);
        const float d = d2 * invd;

        float s0 = fmaf(dx, vx, dy * vy) * invd;
        s0 = fminf(fmaxf(s0, -S_MAX), S_MAX);

        // Arm A: reaches top speed
        const float t_lt1 = (S_MAX - s0) * (1.0f / A_MAX);
        const float d_lt1 = t_lt1 * (s0 + S_MAX) * 0.5f;
        // Arm B: doesn't
        const float sa = s0 * (1.0f / A_MAX);
        const float t_lt2 = sqrtf(fmaf(sa, sa, 2.0f * d * (1.0f / A_MAX))) - sa;

        const float t_lt = (d_lt1 > d) ? t_lt2 : t_lt1;
        const float d_lt = fminf(fmaxf(d_lt1, 0.0f), d);
        const float t_tot = fmaf(d - d_lt, 1.0f / S_MAX, t_lt);

        // T[round(tof)-1] = 0.1 * round(tof)
        const float Tt = 0.1f * rintf(tof);

        const float p = fast_sigmoid(SIG_K * (Tt - t_tot));

        if (j < 11) { s = rec * p; }   // attacker
        else        { q = 1.0f - p; }  // defender
    }

    #pragma unroll
    for (int o = 16; o > 0; o >>= 1) {
        q *= __shfl_xor_sync(0xFFFFFFFFu, q, o);
        s += __shfl_xor_sync(0xFFFFFFFFu, s, o);
    }

    if (j == 0) out[b] = fmaf(s, q, 0.001f);
}

extern "C" void kernel_launch(void* const* d_in, const int* in_sizes, int n_in,
                              void* d_out, int out_size) {
    comp_prob_kernel<<<1, 256>>>((const float*)d_in[0], (float*)d_out);
}

// round 8
// speedup vs baseline: 1.1914x; 1.0062x over previous
#include <cuda_runtime.h>
#include <math.h>

#define C_B  8
#define C_J  22
#define C_F  14
#define A_MAX 7.25f
#define S_MAX 9.25f
#define SIG_K (3.14f / (1.732f * 0.5f))

// Single CTA, 256 threads, warp b = batch b (8 light warps hide the load
// round-trip best -- R5 proved fewer/heavier warps regress). Lane layout:
//   lanes 0..10  : attacker j=lane      -> r = rec_j * p_j   (sum half)
//   lanes 16..26 : defender j=lane-5    -> r = 1 - p_j       (product half)
//   lanes 11..15 : neutral 0, lanes 27..31 : neutral 1
// Mixed-op butterfly: offsets 8,4,2,1 stay inside each 16-lane half; low half
// adds, high half multiplies -- 5 shuffles total instead of 10. Final
// offset-16 shuffle hands lane 0 the defender product.
// Sigmoid via HW tanh.approx.f32 (one MUFU trip): sig(x)=0.5*tanh(x/2)+0.5.
__device__ __forceinline__ float fast_sigmoid(float x) {
    float t;
    asm("tanh.approx.f32 %0, %1;" : "=f"(t) : "f"(0.5f * x));
    return fmaf(0.5f, t, 0.5f);
}

__global__ void __launch_bounds__(256, 1)
comp_prob_kernel(const float* __restrict__ frame, float* __restrict__ out) {
    const int b    = threadIdx.x >> 5;   // warp = batch
    const int lane = threadIdx.x & 31;
    const bool lowHalf = lane < 16;
    // player index: attackers 0..10 in lanes 0..10, defenders 11..21 in 16..26
    const int j = lowHalf ? lane : (lane - 5);
    const bool active = lowHalf ? (lane < 11) : (lane < 27);

    const float* row0 = frame + b * C_J * C_F;

    float r = lowHalf ? 0.0f : 1.0f;   // neutral: add-identity / mul-identity

    if (active) {
        const float* row = row0 + j * C_F;

        const float px = __ldg(row + 1), py = __ldg(row + 2);
        const float vx = __ldg(row + 3), vy = __ldg(row + 4);
        const float rec = lowHalf ? __ldg(row + 10) : 0.0f;
        const float bxf = __ldg(row0 + 11);
        const float byf = __ldg(row0 + 12);
        const float tof = __ldg(row0 + 13);

        // Selected field cell: x = int(bx)+0.5, y = (int(by)+1)-0.5
        const float fx = (float)((int)bxf) + 0.5f;
        const float fy = (float)((int)byf) + 0.5f;

        const float dx = fx - px;
        const float dy = fy - py;
        const float d2 = fmaf(dx, dx, dy * dy);
        const float invd = rsqrtf(d2);
        const float d = d2 * invd;

        float s0 = fmaf(dx, vx, dy * vy) * invd;
        s0 = fminf(fmaxf(s0, -S_MAX), S_MAX);

        // Arm A: reaches top speed
        const float t_lt1 = (S_MAX - s0) * (1.0f / A_MAX);
        const float d_lt1 = t_lt1 * (s0 + S_MAX) * 0.5f;
        // Arm B: doesn't
        const float sa = s0 * (1.0f / A_MAX);
        const float t_lt2 = sqrtf(fmaf(sa, sa, 2.0f * d * (1.0f / A_MAX))) - sa;

        const float t_lt = (d_lt1 > d) ? t_lt2 : t_lt1;
        const float d_lt = fminf(fmaxf(d_lt1, 0.0f), d);
        const float t_tot = fmaf(d - d_lt, 1.0f / S_MAX, t_lt);

        // T[round(tof)-1] = 0.1 * round(tof)
        const float Tt = 0.1f * rintf(tof);

        const float p = fast_sigmoid(SIG_K * (Tt - t_tot));

        r = lowHalf ? (rec * p) : (1.0f - p);
    }

    // Mixed-op butterfly within 16-lane halves.
    #pragma unroll
    for (int o = 8; o > 0; o >>= 1) {
        const float t = __shfl_xor_sync(0xFFFFFFFFu, r, o);
        r = lowHalf ? (r + t) : (r * t);
    }
    // lane 0 holds sum(s); lane 16 holds prod(q). Pair them.
    const float t = __shfl_xor_sync(0xFFFFFFFFu, r, 16);

    if (lane == 0) out[b] = fmaf(r, t, 0.001f);
}

extern "C" void kernel_launch(void* const* d_in, const int* in_sizes, int n_in,
                              void* d_out, int out_size) {
    comp_prob_kernel<<<1, 256>>>((const float*)d_in[0], (float*)d_out);
}